// round 17
// baseline (speedup 1.0000x reference)
#include <cuda_runtime.h>
#include <cuda_bf16.h>
#include <cstdint>

// ---------------- problem constants ----------------
#define D        2048     // EMBED_DIM
#define VQD      256      // VQ_DIM
#define ATO      32000
#define NUMLIM   33000    // ATO + SCO
#define TDLIM    33100    // VQ_START / image_token_offset
#define VQEND    49484
#define NTOK_MAX 65536

// ---------------- scratch (no allocations allowed) ----------------
__device__ int g_cnt;
__device__ int g_pos[NTOK_MAX];
// proj_w split into bf16 hi/lo, [d][k] k-contig, packed 8 bf16 per uint4.
// uint4 typing guarantees 16B alignment BY TYPE (R13/R14 lesson: __align__
// on a bf16 __device__ array is NOT honored -> misaligned address).
__device__ uint4 g_BH4[D * VQD / 8];
__device__ uint4 g_BL4[D * VQD / 8];
// compacted image-token A rows (codebook gather, bf16 hi/lo), slot-major k-contig
__device__ uint4 g_AH4[NTOK_MAX * (VQD / 8)];
__device__ uint4 g_AL4[NTOK_MAX * (VQD / 8)];

__device__ __forceinline__ uint32_t pbf2(float a, float b) {
    __nv_bfloat162 h = __floats2bfloat162_rn(a, b);
    return *(uint32_t*)&h;
}

// ---------------- launch 1: split proj_w -> bf16 hi/lo (packed) + zero counter ----------------
__global__ void split_kernel(const float4* __restrict__ proj_w4) {
    int i = blockIdx.x * blockDim.x + threadIdx.x;    // uint4 index (8 floats)
    if (i == 0) g_cnt = 0;
    if (i < D * VQD / 8) {
        float4 v0 = proj_w4[2 * i];
        float4 v1 = proj_w4[2 * i + 1];
        float f[8] = {v0.x, v0.y, v0.z, v0.w, v1.x, v1.y, v1.z, v1.w};
        uint32_t h[4], l[4];
        #pragma unroll
        for (int p = 0; p < 4; p++) {
            float a = f[2 * p], b = f[2 * p + 1];
            float ah = __bfloat162float(__float2bfloat16_rn(a));
            float bh = __bfloat162float(__float2bfloat16_rn(b));
            h[p] = pbf2(a, b);
            l[p] = pbf2(a - ah, b - bh);
        }
        g_BH4[i] = make_uint4(h[0], h[1], h[2], h[3]);
        g_BL4[i] = make_uint4(l[0], l[1], l[2], l[3]);
    }
}

// ---------------- launch 2: classify + copy; image tokens -> compact + split A row ----------------
__global__ void classify_copy_kernel(const int* __restrict__ x,
                                     const float4* __restrict__ tok_emb,
                                     const float4* __restrict__ added_emb,
                                     const float4* __restrict__ nums_emb,
                                     const float4* __restrict__ codebook4,
                                     float4* __restrict__ out, int n_tok) {
    int gw   = (blockIdx.x * blockDim.x + threadIdx.x) >> 5;
    int lane = threadIdx.x & 31;
    if (gw >= n_tok) return;
    int t = x[gw];

    const float4* src;
    if (t < ATO) {
        src = tok_emb + (size_t)t * (D / 4);
    } else if (t < NUMLIM) {
        src = nums_emb + (size_t)(t - ATO) * (D / 4);
    } else if (t < TDLIM) {
        src = added_emb + (size_t)(t - NUMLIM) * (D / 4);
    } else if (t < VQEND) {
        // image token: compact slot + gather/split codebook row (8 floats/lane)
        int s = 0;
        if (lane == 0) {
            s = atomicAdd(&g_cnt, 1);
            g_pos[s] = gw;
        }
        s = __shfl_sync(0xffffffffu, s, 0);
        int cb = t - TDLIM;
        const float4* crow = codebook4 + (size_t)cb * (VQD / 4) + lane * 2;
        float4 v0 = crow[0];
        float4 v1 = crow[1];
        float f[8] = {v0.x, v0.y, v0.z, v0.w, v1.x, v1.y, v1.z, v1.w};
        uint32_t h[4], l[4];
        #pragma unroll
        for (int p = 0; p < 4; p++) {
            float a = f[2 * p], b = f[2 * p + 1];
            float ah = __bfloat162float(__float2bfloat16_rn(a));
            float bh = __bfloat162float(__float2bfloat16_rn(b));
            h[p] = pbf2(a, b);
            l[p] = pbf2(a - ah, b - bh);
        }
        g_AH4[(size_t)s * 32 + lane] = make_uint4(h[0], h[1], h[2], h[3]);
        g_AL4[(size_t)s * 32 + lane] = make_uint4(l[0], l[1], l[2], l[3]);
        return;
    } else {
        src = nullptr;
    }

    float4* dst = out + (size_t)gw * (D / 4);
    if (src) {
        #pragma unroll
        for (int i = 0; i < (D / 4) / 32; i++)
            dst[lane + 32 * i] = src[lane + 32 * i];
    } else {
        float4 z = make_float4(0.f, 0.f, 0.f, 0.f);
        #pragma unroll
        for (int i = 0; i < (D / 4) / 32; i++)
            dst[lane + 32 * i] = z;
    }
}

// ---------------- launch 3: HMMA (bf16 3-term split) image GEMM ----------------
// Block: 128 tokens x 1024 dims (grid.x = 2). 8 warps as 2(m) x 4(n): warp
// tile m64 x n32 (1:4 LDSM:mma). A (both 128-k chunks, hi+lo = 128KB) resident
// in smem for the whole block; B tiles (n128 x k128 hi+lo = 64KB) streamed.
#define GT      128
#define NSPLIT  2
#define NBLK    (D / NSPLIT)   // 1024
#define NTILE   128
#define KCH     128

// smem plane bases (bytes): A hi kc0/kc1, A lo kc0/kc1, B hi, B lo
#define AH0 0
#define AH1 32768
#define AL0 65536
#define AL1 98304
#define BHS 131072
#define BLS 163840
#define SMEM_BYTES 196608

// swizzled offset within a 128row x 128k bf16 plane (256B rows, 16x16B groups;
// group ^= row&7 -> conflict-free ldmatrix and stores)
__device__ __forceinline__ uint32_t sw2(int row, int k) {
    return ((uint32_t)row << 8)
         + ((uint32_t)((((k >> 3) & 15) ^ (row & 7))) << 4)
         + ((uint32_t)(k & 7) << 1);
}

__device__ __forceinline__ uint32_t smem_u32(const void* p) {
    uint32_t a;
    asm("{ .reg .u64 t; cvta.to.shared.u64 t, %1; cvt.u32.u64 %0, t; }" : "=r"(a) : "l"(p));
    return a;
}
__device__ __forceinline__ void ldm4(uint32_t* r, uint32_t addr) {
    asm volatile("ldmatrix.sync.aligned.m8n8.x4.shared.b16 {%0,%1,%2,%3}, [%4];"
        : "=r"(r[0]), "=r"(r[1]), "=r"(r[2]), "=r"(r[3]) : "r"(addr));
}
__device__ __forceinline__ void mma16816(float* c, const uint32_t* a, const uint32_t* b) {
    asm volatile("mma.sync.aligned.m16n8k16.row.col.f32.bf16.bf16.f32 "
        "{%0,%1,%2,%3}, {%4,%5,%6,%7}, {%8,%9}, {%0,%1,%2,%3};"
        : "+f"(c[0]), "+f"(c[1]), "+f"(c[2]), "+f"(c[3])
        : "r"(a[0]), "r"(a[1]), "r"(a[2]), "r"(a[3]), "r"(b[0]), "r"(b[1]));
}

__global__ void __launch_bounds__(256, 1)
img_hmma_kernel(float* __restrict__ out) {
    extern __shared__ __align__(16) char smem[];
    __shared__ int s_pos[GT];

    int n_img = g_cnt;
    int t0 = blockIdx.y * GT;
    if (t0 >= n_img) return;

    uint32_t sb = smem_u32(smem);
    int tid  = threadIdx.x;
    int lane = tid & 31;
    int wid  = tid >> 5;
    int wm   = wid >> 2;          // 0..1 -> m offset 0/64
    int wn   = wid & 3;           // 0..3 -> n offset 0/32/64/96

    if (tid < GT) {
        int gi = t0 + tid;
        s_pos[tid] = (gi < n_img) ? g_pos[gi] : -1;
    }

    // ---- load whole A block (128 rows x 256 k, hi+lo) into resident smem ----
    // rows beyond n_img read stale slots; their results are masked at epilogue.
    #pragma unroll
    for (int i = 0; i < 16; i++) {
        int e   = tid + i * 256;          // 0..4095
        int row = e >> 5;
        int kg  = e & 31;                 // uint4 group over k256
        int kc  = kg >> 4;
        int kgl = kg & 15;
        size_t u = (size_t)(t0 + row) * 32 + kg;
        uint32_t o = (kc ? AH1 : AH0) + sw2(row, kgl << 3);
        *(uint4*)(smem + o) = g_AH4[u];
        *(uint4*)(smem + o + AL0) = g_AL4[u];
    }

    // per-lane ldmatrix address components (mapping validated in R16)
    int g = lane >> 3, r = lane & 7;
    int am_base = wm * 64 + ((g & 1) << 3) + r;       // + 16*mf
    int ak_add  = (g >> 1) << 3;
    int bn_base = wn * 32 + ((g >> 1) << 3) + r;      // + 16*nf2
    int bk_add  = (g & 1) << 3;

    for (int nt = 0; nt < NBLK / NTILE; nt++) {       // 8 n-tiles
        int dt = blockIdx.x * NBLK + nt * NTILE;

        float acc[4][4][4];
        #pragma unroll
        for (int mf = 0; mf < 4; mf++)
            #pragma unroll
            for (int nf = 0; nf < 4; nf++)
                #pragma unroll
                for (int q = 0; q < 4; q++) acc[mf][nf][q] = 0.f;

        #pragma unroll
        for (int kc = 0; kc < 2; kc++) {
            __syncthreads();   // prior B tile fully consumed (also A stores, 1st iter)
            // ---- stream B tile: 128 dims x 128 k, hi+lo ----
            #pragma unroll
            for (int i = 0; i < 8; i++) {
                int e   = tid + i * 256;      // 0..2047
                int row = e >> 4;
                int kg  = e & 15;
                size_t u = (size_t)(dt + row) * 32 + kc * 16 + kg;
                uint32_t o = sw2(row, kg << 3);
                *(uint4*)(smem + BHS + o) = g_BH4[u];
                *(uint4*)(smem + BLS + o) = g_BL4[u];
            }
            __syncthreads();

            uint32_t abh = sb + (kc ? AH1 : AH0);
            uint32_t abl = abh + AL0;

            #pragma unroll
            for (int k16 = 0; k16 < KCH / 16; k16++) {
                int k0 = k16 << 4;
                uint32_t ah[4][4], al[4][4], bh[2][4], bl[2][4];
                #pragma unroll
                for (int mf = 0; mf < 4; mf++) {
                    uint32_t ao = sw2(am_base + 16 * mf, k0 + ak_add);
                    ldm4(ah[mf], abh + ao);
                    ldm4(al[mf], abl + ao);
                }
                #pragma unroll
                for (int n2 = 0; n2 < 2; n2++) {
                    uint32_t bo = sw2(bn_base + 16 * n2, k0 + bk_add);
                    ldm4(bh[n2], sb + BHS + bo);
                    ldm4(bl[n2], sb + BLS + bo);
                }
                // term passes separated -> dependent accs 16 instructions apart
                #pragma unroll
                for (int mf = 0; mf < 4; mf++)
                    #pragma unroll
                    for (int nf = 0; nf < 4; nf++)
                        mma16816(acc[mf][nf], ah[mf], bh[nf >> 1] + (nf & 1) * 2);
                #pragma unroll
                for (int mf = 0; mf < 4; mf++)
                    #pragma unroll
                    for (int nf = 0; nf < 4; nf++)
                        mma16816(acc[mf][nf], ah[mf], bl[nf >> 1] + (nf & 1) * 2);
                #pragma unroll
                for (int mf = 0; mf < 4; mf++)
                    #pragma unroll
                    for (int nf = 0; nf < 4; nf++)
                        mma16816(acc[mf][nf], al[mf], bh[nf >> 1] + (nf & 1) * 2);
            }
        }

        // ---- epilogue: scatter D rows via s_pos ----
        #pragma unroll
        for (int mf = 0; mf < 4; mf++) {
            int mrow = wm * 64 + mf * 16 + (lane >> 2);
            int p0 = s_pos[mrow];
            int p1 = s_pos[mrow + 8];
            #pragma unroll
            for (int nf = 0; nf < 4; nf++) {
                int col = dt + wn * 32 + nf * 8 + (lane & 3) * 2;
                if (p0 >= 0)
                    *(float2*)(out + (size_t)p0 * D + col) =
                        make_float2(acc[mf][nf][0], acc[mf][nf][1]);
                if (p1 >= 0)
                    *(float2*)(out + (size_t)p1 * D + col) =
                        make_float2(acc[mf][nf][2], acc[mf][nf][3]);
            }
        }
    }
}

// ---------------- launcher ----------------
extern "C" void kernel_launch(void* const* d_in, const int* in_sizes, int n_in,
                              void* d_out, int out_size) {
    const int*   x        = (const int*)d_in[0];
    const float* tok_emb  = (const float*)d_in[1];
    const float* added    = (const float*)d_in[2];
    const float* nums     = (const float*)d_in[3];
    const float* codebook = (const float*)d_in[4];
    const float* proj_w   = (const float*)d_in[5];
    float*       out      = (float*)d_out;
    int n_tok = in_sizes[0];

    cudaFuncSetAttribute(img_hmma_kernel,
                         cudaFuncAttributeMaxDynamicSharedMemorySize, SMEM_BYTES);

    split_kernel<<<(D * VQD / 8 + 255) / 256, 256>>>((const float4*)proj_w);

    classify_copy_kernel<<<(n_tok + 7) / 8, 256>>>(
        x, (const float4*)tok_emb, (const float4*)added,
        (const float4*)nums, (const float4*)codebook, (float4*)out, n_tok);

    int mtiles = (n_tok + GT - 1) / GT;     // worst case: all tokens are images
    img_hmma_kernel<<<dim3(NSPLIT, mtiles), 256, SMEM_BYTES>>>(out);
}